// round 7
// baseline (speedup 1.0000x reference)
#include <cuda_runtime.h>
#include <cuda_bf16.h>
#include <cstdint>

#define DIM    1024
#define NHEADS 16
#define HDIM   64
#define BATCH  2
#define SEQ    2048
#define MROWS  4096

// ---------------------------------------------------------------------------
// Packed bf16 hi/lo global scratch (u32 = 2 bf16, k-major pairs)
// ---------------------------------------------------------------------------
__device__ __align__(128) uint32_t g_xh [MROWS * 512], g_xl [MROWS * 512];
__device__ __align__(128) uint32_t g_wqh[3072 * 512],  g_wql[3072 * 512];
__device__ __align__(128) uint32_t g_wph[1024 * 512],  g_wpl[1024 * 512];
// QKV: [s_idx(3)][bh(32)][seq(2048)][32 u32]   (Q pre-scaled by 0.125)
__device__ __align__(128) uint32_t g_qkvh[3u * 2097152], g_qkvl[3u * 2097152];
__device__ __align__(128) uint32_t g_aoh[MROWS * 512], g_aol[MROWS * 512];

// ---------------------------------------------------------------------------
// Helpers
// ---------------------------------------------------------------------------
__device__ __forceinline__ uint32_t smem_u32(const void* p) {
    uint32_t a;
    asm("{ .reg .u64 t; cvta.to.shared.u64 t, %1; cvt.u32.u64 %0, t; }" : "=r"(a) : "l"(p));
    return a;
}
__device__ __forceinline__ void ldsm4(uint32_t r[4], uint32_t addr) {
    asm volatile("ldmatrix.sync.aligned.m8n8.x4.shared.b16 {%0,%1,%2,%3}, [%4];"
                 : "=r"(r[0]), "=r"(r[1]), "=r"(r[2]), "=r"(r[3]) : "r"(addr));
}
__device__ __forceinline__ void ldsm4t(uint32_t r[4], uint32_t addr) {
    asm volatile("ldmatrix.sync.aligned.m8n8.x4.trans.shared.b16 {%0,%1,%2,%3}, [%4];"
                 : "=r"(r[0]), "=r"(r[1]), "=r"(r[2]), "=r"(r[3]) : "r"(addr));
}
__device__ __forceinline__ void mma_bf(float c[4], const uint32_t a[4], const uint32_t b[2]) {
    asm volatile(
        "mma.sync.aligned.m16n8k16.row.col.f32.bf16.bf16.f32 "
        "{%0,%1,%2,%3}, {%4,%5,%6,%7}, {%8,%9}, {%0,%1,%2,%3};"
        : "+f"(c[0]), "+f"(c[1]), "+f"(c[2]), "+f"(c[3])
        : "r"(a[0]), "r"(a[1]), "r"(a[2]), "r"(a[3]), "r"(b[0]), "r"(b[1]));
}
__device__ __forceinline__ uint32_t packbf(float x, float y) {
    unsigned short ux = __bfloat16_as_ushort(__float2bfloat16(x));
    unsigned short uy = __bfloat16_as_ushort(__float2bfloat16(y));
    return (uint32_t)ux | ((uint32_t)uy << 16);
}
__device__ __forceinline__ void hilo2(float x, float y, uint32_t& hi, uint32_t& lo) {
    float hx = __bfloat162float(__float2bfloat16(x));
    float hy = __bfloat162float(__float2bfloat16(y));
    hi = packbf(x, y);
    lo = packbf(x - hx, y - hy);
}
__device__ __forceinline__ void cpa16(uint32_t dst, const void* src) {
    asm volatile("cp.async.cg.shared.global [%0], [%1], 16;" :: "r"(dst), "l"(src));
}
#define CP_COMMIT() asm volatile("cp.async.commit_group;" ::: "memory")
#define CP_WAIT(n)  asm volatile("cp.async.wait_group %0;" :: "n"(n) : "memory")

// ---------------------------------------------------------------------------
// Split fp32 [rows][1024] -> packed hi/lo u32 [rows][512]
// ---------------------------------------------------------------------------
__global__ __launch_bounds__(256)
void split_k(const float* __restrict__ in, uint32_t* __restrict__ hi,
             uint32_t* __restrict__ lo, int n4)
{
    int g = blockIdx.x * 256 + threadIdx.x;
    if (g >= n4) return;
    float4 v = ((const float4*)in)[g];
    uint32_t h0, l0, h1, l1;
    hilo2(v.x, v.y, h0, l0);
    hilo2(v.z, v.w, h1, l1);
    ((uint2*)hi)[g] = make_uint2(h0, h1);
    ((uint2*)lo)[g] = make_uint2(l0, l1);
}

// ---------------------------------------------------------------------------
// GEMM: C[M,N] = A[M,K] @ B[N,K]^T, bf16 hi/lo 3-MMA, cp.async 3-stage BK=32.
// Block 128x128, 256 thr (8 warps, 64x32 warp tile), 2 CTAs/SM.
// smem/stage 32KB: A[128][128B] + B[128][128B]; row = 8x16B chunks
// (0-3 hi, 4-7 lo), phys chunk = logical ^ (row&7).
// EPI 0: split-store into g_qkvh/l (Q scaled by 0.125). EPI 1: fp32 + bias.
// ---------------------------------------------------------------------------
template <int EPI>
__global__ __launch_bounds__(256, 2)
void mm2(const uint32_t* __restrict__ Ah, const uint32_t* __restrict__ Al,
         const uint32_t* __restrict__ Bh, const uint32_t* __restrict__ Bl,
         const float* __restrict__ bias, float* __restrict__ Cout,
         uint32_t* __restrict__ qh, uint32_t* __restrict__ ql,
         int N, int K)
{
    extern __shared__ __align__(128) uint32_t sm[];
    const int tid = threadIdx.x, lane = tid & 31, wid = tid >> 5;
    const int m0 = blockIdx.y * 128, n0 = blockIdx.x * 128;
    const int wm = (wid & 1) * 64, wn = (wid >> 1) * 32;
    const uint32_t base = smem_u32(sm);
    const int T  = K >> 5;   // k32 steps
    const int KC = K >> 3;   // 16B chunks per row

    const int arow = lane & 15, aco = lane >> 4;
    const int brow = (lane & 7) | ((lane & 16) >> 1), bco = (lane & 8) >> 3;

    auto issue = [&](int t) {
        int st  = t % 3;
        int kc0 = t << 2;
        #pragma unroll
        for (int it = 0; it < 8; it++) {
            int idx = tid + it * 256;              // 0..2047 (A first, then B)
            int row = (idx >> 3) & 127;
            int ch  = idx & 7;
            bool isB = idx >= 1024;
            const uint32_t* sp = isB ? (ch < 4 ? Bh : Bl) : (ch < 4 ? Ah : Al);
            int grow = (isB ? n0 : m0) + row;
            const void* src = sp + ((size_t)grow * KC + kc0 + (ch & 3)) * 4;
            uint32_t dst = base + st * 32768 + (isB ? 16384 : 0)
                         + row * 128 + ((ch ^ (row & 7)) * 16);
            cpa16(dst, src);
        }
    };

    float acc[4][4][4] = {};

    issue(0); CP_COMMIT();
    issue(1); CP_COMMIT();

    for (int t = 0; t < T; t++) {
        if (t + 2 < T) { issue(t + 2); CP_COMMIT(); CP_WAIT(2); }
        else           { CP_WAIT(0); }
        __syncthreads();

        const uint32_t aOff = base + (t % 3) * 32768;
        const uint32_t bOff = aOff + 16384;
        #pragma unroll
        for (int kk = 0; kk < 2; kk++) {
            uint32_t aH[4][4], aL[4][4], bH[2][4], bL[2][4];
            #pragma unroll
            for (int mt = 0; mt < 4; mt++) {
                int r = wm + mt * 16 + arow;
                int c = (kk * 2 + aco) ^ (r & 7);
                ldsm4(aH[mt], aOff + r * 128 + c * 16);
                ldsm4(aL[mt], aOff + r * 128 + (c ^ 4) * 16);
            }
            #pragma unroll
            for (int g = 0; g < 2; g++) {
                int r = wn + g * 16 + brow;
                int c = (kk * 2 + bco) ^ (r & 7);
                ldsm4(bH[g], bOff + r * 128 + c * 16);
                ldsm4(bL[g], bOff + r * 128 + (c ^ 4) * 16);
            }
            #pragma unroll
            for (int mt = 0; mt < 4; mt++)
                #pragma unroll
                for (int nt = 0; nt < 4; nt++) {
                    const uint32_t* bh = &bH[nt >> 1][(nt & 1) * 2];
                    const uint32_t* bl = &bL[nt >> 1][(nt & 1) * 2];
                    mma_bf(acc[mt][nt], aH[mt], bh);
                    mma_bf(acc[mt][nt], aH[mt], bl);
                    mma_bf(acc[mt][nt], aL[mt], bh);
                }
        }
        __syncthreads();
    }

    const int r = lane >> 2, j = (lane & 3) * 2;
    if (EPI == 0) {
        const int sidx = n0 >> 10;
        const float qs = (sidx == 0) ? 0.125f : 1.0f;
        uint32_t* H = qh + (size_t)sidx * 2097152;
        uint32_t* L = ql + (size_t)sidx * 2097152;
        #pragma unroll
        for (int mt = 0; mt < 4; mt++) {
            int mA = m0 + wm + mt * 16 + r;
            int b  = mA >> 11, q = mA & 2047;
            #pragma unroll
            for (int nt = 0; nt < 4; nt++) {
                int n = n0 + wn + nt * 8 + j;
                int rin = n & 1023, h = rin >> 6, d = rin & 63;
                size_t o1 = (((size_t)(b * 16 + h)) * 2048 + q) * 32 + (d >> 1);
                uint32_t hh, ll;
                hilo2(acc[mt][nt][0] * qs, acc[mt][nt][1] * qs, hh, ll);
                H[o1] = hh; L[o1] = ll;
                hilo2(acc[mt][nt][2] * qs, acc[mt][nt][3] * qs, hh, ll);
                H[o1 + 8 * 32] = hh; L[o1 + 8 * 32] = ll;
            }
        }
    } else {
        #pragma unroll
        for (int mt = 0; mt < 4; mt++) {
            int mA = m0 + wm + mt * 16 + r;
            #pragma unroll
            for (int nt = 0; nt < 4; nt++) {
                int c = n0 + wn + nt * 8 + j;
                float b0 = bias[c], b1 = bias[c + 1];
                *(float2*)(Cout + (size_t)mA * N + c) =
                    make_float2(acc[mt][nt][0] + b0, acc[mt][nt][1] + b1);
                *(float2*)(Cout + (size_t)(mA + 8) * N + c) =
                    make_float2(acc[mt][nt][2] + b0, acc[mt][nt][3] + b1);
            }
        }
    }
}

// ---------------------------------------------------------------------------
// Flash attention, HMMA hi/lo, cp.async 2-stage 64-key KV, 2 CTAs/SM.
// Block = 128 queries of one (b,h), 256 thr / 8 warps (warp owns 16 rows).
// smem (bytes): Qhi 0 (16KB), Qlo 16384; KV stage s at 32768+s*32768:
//   Khi +0, Klo +8192, Vhi +16384, Vlo +24576.  Total 96KB.
// ---------------------------------------------------------------------------
__global__ __launch_bounds__(256, 2)
void flash2()
{
    extern __shared__ __align__(128) uint32_t sm[];
    const int tid = threadIdx.x, lane = tid & 31, w = tid >> 5;
    const int bh = blockIdx.y, b = bh >> 4, h = bh & 15;
    const int q0 = blockIdx.x * 128;
    const uint32_t base = smem_u32(sm);

    const int arow = lane & 15, aco = lane >> 4;
    const int brow = (lane & 7) | ((lane & 16) >> 1), bco = (lane & 8) >> 3;

    // Q preload (hi+lo): 2048 16B-chunks
    #pragma unroll
    for (int it = 0; it < 8; it++) {
        int idx = tid + it * 256;
        int lohf = idx >= 1024;
        int row = (idx >> 3) & 127, ch = idx & 7;
        const uint32_t* sp = lohf ? g_qkvl : g_qkvh;
        const void* src = sp + ((size_t)bh * 2048 + q0 + row) * 32 + ch * 4;
        uint32_t dst = base + lohf * 16384 + row * 128 + ((ch ^ (row & 7)) * 16);
        cpa16(dst, src);
    }
    CP_COMMIT();

    auto issueKV = [&](int t) {
        int st = t & 1, s0 = t * 64;
        #pragma unroll
        for (int it = 0; it < 8; it++) {
            int idx = tid + it * 256;              // 0..2047
            int tensor = idx >> 10;                // 0=K, 1=V
            int lohf = (idx >> 9) & 1;
            int row = (idx >> 3) & 63, ch = idx & 7;
            const uint32_t* sp = lohf ? g_qkvl : g_qkvh;
            const void* src = sp + (size_t)(1 + tensor) * 2097152
                            + ((size_t)bh * 2048 + s0 + row) * 32 + ch * 4;
            uint32_t dst = base + 32768 + st * 32768 + tensor * 16384
                         + lohf * 8192 + row * 128 + ((ch ^ (row & 7)) * 16);
            cpa16(dst, src);
        }
    };

    issueKV(0); CP_COMMIT();

    float m_a = -1e30f, m_b = -1e30f, l_a = 0.f, l_b = 0.f;
    float o[8][4] = {};

    const int NT = SEQ / 64;   // 32
    for (int t = 0; t < NT; t++) {
        if (t + 1 < NT) { issueKV(t + 1); CP_COMMIT(); CP_WAIT(1); }
        else            { CP_WAIT(0); }
        __syncthreads();

        const uint32_t kBase = base + 32768 + (t & 1) * 32768;
        const uint32_t vBase = kBase + 16384;

        // S = Q K^T (Q pre-scaled by 0.125). 64 keys = 8 n8 tiles.
        float s[8][4] = {};
        #pragma unroll
        for (int kk = 0; kk < 4; kk++) {
            uint32_t aH[4], aL[4];
            {
                int r = w * 16 + arow;
                int c = (kk * 2 + aco) ^ (r & 7);
                ldsm4(aH, base + r * 128 + c * 16);
                ldsm4(aL, base + 16384 + r * 128 + c * 16);
            }
            #pragma unroll
            for (int g = 0; g < 4; g++) {
                int rb = g * 16 + brow;
                int cb = (kk * 2 + bco) ^ (rb & 7);
                uint32_t bHf[4], bLf[4];
                ldsm4(bHf, kBase + rb * 128 + cb * 16);
                ldsm4(bLf, kBase + 8192 + rb * 128 + cb * 16);
                mma_bf(s[2 * g],     aH, &bHf[0]);
                mma_bf(s[2 * g],     aH, &bLf[0]);
                mma_bf(s[2 * g],     aL, &bHf[0]);
                mma_bf(s[2 * g + 1], aH, &bHf[2]);
                mma_bf(s[2 * g + 1], aH, &bLf[2]);
                mma_bf(s[2 * g + 1], aL, &bHf[2]);
            }
        }

        // Online softmax (rows lane>>2 and +8; 4-lane group reduce)
        float mxa = -1e30f, mxb = -1e30f;
        #pragma unroll
        for (int nt = 0; nt < 8; nt++) {
            mxa = fmaxf(mxa, fmaxf(s[nt][0], s[nt][1]));
            mxb = fmaxf(mxb, fmaxf(s[nt][2], s[nt][3]));
        }
        mxa = fmaxf(mxa, __shfl_xor_sync(0xffffffffu, mxa, 1));
        mxa = fmaxf(mxa, __shfl_xor_sync(0xffffffffu, mxa, 2));
        mxb = fmaxf(mxb, __shfl_xor_sync(0xffffffffu, mxb, 1));
        mxb = fmaxf(mxb, __shfl_xor_sync(0xffffffffu, mxb, 2));
        float mna = fmaxf(m_a, mxa), mnb = fmaxf(m_b, mxb);
        float alA = __expf(m_a - mna), alB = __expf(m_b - mnb);
        m_a = mna; m_b = mnb;
        float suma = 0.f, sumb = 0.f;
        #pragma unroll
        for (int nt = 0; nt < 8; nt++) {
            s[nt][0] = __expf(s[nt][0] - mna); suma += s[nt][0];
            s[nt][1] = __expf(s[nt][1] - mna); suma += s[nt][1];
            s[nt][2] = __expf(s[nt][2] - mnb); sumb += s[nt][2];
            s[nt][3] = __expf(s[nt][3] - mnb); sumb += s[nt][3];
        }
        suma += __shfl_xor_sync(0xffffffffu, suma, 1);
        suma += __shfl_xor_sync(0xffffffffu, suma, 2);
        sumb += __shfl_xor_sync(0xffffffffu, sumb, 1);
        sumb += __shfl_xor_sync(0xffffffffu, sumb, 2);
        l_a = l_a * alA + suma;
        l_b = l_b * alB + sumb;
        #pragma unroll
        for (int dt = 0; dt < 8; dt++) {
            o[dt][0] *= alA; o[dt][1] *= alA;
            o[dt][2] *= alB; o[dt][3] *= alB;
        }

        // O += P V  (kc = 4 key-chunks of 16; dt = 8 d-tiles)
        #pragma unroll
        for (int kc = 0; kc < 4; kc++) {
            uint32_t pH[4], pL[4];
            hilo2(s[2 * kc][0],     s[2 * kc][1],     pH[0], pL[0]);
            hilo2(s[2 * kc][2],     s[2 * kc][3],     pH[1], pL[1]);
            hilo2(s[2 * kc + 1][0], s[2 * kc + 1][1], pH[2], pL[2]);
            hilo2(s[2 * kc + 1][2], s[2 * kc + 1][3], pH[3], pL[3]);
            #pragma unroll
            for (int g = 0; g < 4; g++) {
                int rv = kc * 16 + arow;
                int cv = (g * 2 + aco) ^ (rv & 7);
                uint32_t vHf[4], vLf[4];
                ldsm4t(vHf, vBase + rv * 128 + cv * 16);
                ldsm4t(vLf, vBase + 8192 + rv * 128 + cv * 16);
                mma_bf(o[2 * g],     pH, &vHf[0]);
                mma_bf(o[2 * g],     pH, &vLf[0]);
                mma_bf(o[2 * g],     pL, &vHf[0]);
                mma_bf(o[2 * g + 1], pH, &vHf[2]);
                mma_bf(o[2 * g + 1], pH, &vLf[2]);
                mma_bf(o[2 * g + 1], pL, &vHf[2]);
            }
        }
        __syncthreads();   // protect 2-stage ring (issueKV(t+2) rewrites stage t)
    }

    // Epilogue: normalize, pack hi/lo to g_aoh/g_aol [m][512]
    float ia = 1.f / l_a, ib = 1.f / l_b;
    size_t mA = (size_t)b * SEQ + q0 + w * 16 + (lane >> 2);
    #pragma unroll
    for (int dt = 0; dt < 8; dt++) {
        int c  = dt * 8 + (lane & 3) * 2;
        int ci = h * 32 + (c >> 1);
        uint32_t hh, ll;
        hilo2(o[dt][0] * ia, o[dt][1] * ia, hh, ll);
        g_aoh[mA * 512 + ci] = hh; g_aol[mA * 512 + ci] = ll;
        hilo2(o[dt][2] * ib, o[dt][3] * ib, hh, ll);
        g_aoh[(mA + 8) * 512 + ci] = hh; g_aol[(mA + 8) * 512 + ci] = ll;
    }
}

// ---------------------------------------------------------------------------
extern "C" void kernel_launch(void* const* d_in, const int* in_sizes, int n_in,
                              void* d_out, int out_size)
{
    const float* x      = (const float*)d_in[0];
    const float* w_qkv  = (const float*)d_in[1];
    const float* w_proj = (const float*)d_in[2];
    const float* b_proj = (const float*)d_in[3];
    float* out = (float*)d_out;

    void *pxh, *pxl, *pwqh, *pwql, *pwph, *pwpl, *pqh, *pql, *paoh, *paol;
    cudaGetSymbolAddress(&pxh, g_xh);   cudaGetSymbolAddress(&pxl, g_xl);
    cudaGetSymbolAddress(&pwqh, g_wqh); cudaGetSymbolAddress(&pwql, g_wql);
    cudaGetSymbolAddress(&pwph, g_wph); cudaGetSymbolAddress(&pwpl, g_wpl);
    cudaGetSymbolAddress(&pqh, g_qkvh); cudaGetSymbolAddress(&pql, g_qkvl);
    cudaGetSymbolAddress(&paoh, g_aoh); cudaGetSymbolAddress(&paol, g_aol);

    cudaFuncSetAttribute(mm2<0>, cudaFuncAttributeMaxDynamicSharedMemorySize, 98304);
    cudaFuncSetAttribute(mm2<1>, cudaFuncAttributeMaxDynamicSharedMemorySize, 98304);
    cudaFuncSetAttribute(flash2, cudaFuncAttributeMaxDynamicSharedMemorySize, 98304);

    // 1) Splits
    split_k<<<4096, 256>>>(x,      (uint32_t*)pxh,  (uint32_t*)pxl,  1048576);
    split_k<<<3072, 256>>>(w_qkv,  (uint32_t*)pwqh, (uint32_t*)pwql, 786432);
    split_k<<<1024, 256>>>(w_proj, (uint32_t*)pwph, (uint32_t*)pwpl, 262144);

    // 2) QKV projection -> split Q/K/V (Q scaled)
    mm2<0><<<dim3(24, 32), 256, 98304>>>(
        (uint32_t*)pxh, (uint32_t*)pxl, (uint32_t*)pwqh, (uint32_t*)pwql,
        nullptr, nullptr, (uint32_t*)pqh, (uint32_t*)pql, 3072, 1024);

    // 3) Attention: 128 queries/block per (b,h)
    flash2<<<dim3(16, 32), 256, 98304>>>();

    // 4) Output projection + bias
    mm2<1><<<dim3(8, 32), 256, 98304>>>(
        (uint32_t*)paoh, (uint32_t*)paol, (uint32_t*)pwph, (uint32_t*)pwpl,
        b_proj, out, nullptr, nullptr, 1024, 1024);
}

// round 8
// speedup vs baseline: 1.0152x; 1.0152x over previous
#include <cuda_runtime.h>
#include <cuda_bf16.h>
#include <cstdint>

#define DIM    1024
#define NHEADS 16
#define HDIM   64
#define BATCH  2
#define SEQ    2048
#define MROWS  4096

// ---------------------------------------------------------------------------
// Packed bf16 hi/lo global scratch (u32 = 2 bf16, k-major pairs)
// ---------------------------------------------------------------------------
__device__ __align__(128) uint32_t g_xh [MROWS * 512], g_xl [MROWS * 512];
__device__ __align__(128) uint32_t g_wqh[3072 * 512],  g_wql[3072 * 512];
__device__ __align__(128) uint32_t g_wph[1024 * 512],  g_wpl[1024 * 512];
// QKV: [s_idx(3)][bh(32)][seq(2048)][32 u32]   (Q pre-scaled by 0.125)
__device__ __align__(128) uint32_t g_qkvh[3u * 2097152], g_qkvl[3u * 2097152];
__device__ __align__(128) uint32_t g_aoh[MROWS * 512], g_aol[MROWS * 512];

// ---------------------------------------------------------------------------
// Helpers
// ---------------------------------------------------------------------------
__device__ __forceinline__ uint32_t smem_u32(const void* p) {
    uint32_t a;
    asm("{ .reg .u64 t; cvta.to.shared.u64 t, %1; cvt.u32.u64 %0, t; }" : "=r"(a) : "l"(p));
    return a;
}
__device__ __forceinline__ void ldsm4(uint32_t r[4], uint32_t addr) {
    asm volatile("ldmatrix.sync.aligned.m8n8.x4.shared.b16 {%0,%1,%2,%3}, [%4];"
                 : "=r"(r[0]), "=r"(r[1]), "=r"(r[2]), "=r"(r[3]) : "r"(addr));
}
__device__ __forceinline__ void ldsm4t(uint32_t r[4], uint32_t addr) {
    asm volatile("ldmatrix.sync.aligned.m8n8.x4.trans.shared.b16 {%0,%1,%2,%3}, [%4];"
                 : "=r"(r[0]), "=r"(r[1]), "=r"(r[2]), "=r"(r[3]) : "r"(addr));
}
__device__ __forceinline__ void mma_bf(float c[4], const uint32_t a[4], const uint32_t b[2]) {
    asm volatile(
        "mma.sync.aligned.m16n8k16.row.col.f32.bf16.bf16.f32 "
        "{%0,%1,%2,%3}, {%4,%5,%6,%7}, {%8,%9}, {%0,%1,%2,%3};"
        : "+f"(c[0]), "+f"(c[1]), "+f"(c[2]), "+f"(c[3])
        : "r"(a[0]), "r"(a[1]), "r"(a[2]), "r"(a[3]), "r"(b[0]), "r"(b[1]));
}
__device__ __forceinline__ uint32_t packbf(float x, float y) {
    unsigned short ux = __bfloat16_as_ushort(__float2bfloat16(x));
    unsigned short uy = __bfloat16_as_ushort(__float2bfloat16(y));
    return (uint32_t)ux | ((uint32_t)uy << 16);
}
__device__ __forceinline__ void hilo2(float x, float y, uint32_t& hi, uint32_t& lo) {
    float hx = __bfloat162float(__float2bfloat16(x));
    float hy = __bfloat162float(__float2bfloat16(y));
    hi = packbf(x, y);
    lo = packbf(x - hx, y - hy);
}
__device__ __forceinline__ void cpa16(uint32_t dst, const void* src) {
    asm volatile("cp.async.cg.shared.global [%0], [%1], 16;" :: "r"(dst), "l"(src));
}
#define CP_COMMIT() asm volatile("cp.async.commit_group;" ::: "memory")
#define CP_WAIT(n)  asm volatile("cp.async.wait_group %0;" :: "n"(n) : "memory")

// ---------------------------------------------------------------------------
// Split fp32 [rows][1024] -> packed hi/lo u32 [rows][512]
// ---------------------------------------------------------------------------
__global__ __launch_bounds__(256)
void split_k(const float* __restrict__ in, uint32_t* __restrict__ hi,
             uint32_t* __restrict__ lo, int n4)
{
    int g = blockIdx.x * 256 + threadIdx.x;
    if (g >= n4) return;
    float4 v = ((const float4*)in)[g];
    uint32_t h0, l0, h1, l1;
    hilo2(v.x, v.y, h0, l0);
    hilo2(v.z, v.w, h1, l1);
    ((uint2*)hi)[g] = make_uint2(h0, h1);
    ((uint2*)lo)[g] = make_uint2(l0, l1);
}

// ---------------------------------------------------------------------------
// GEMM: C[M,N] = A[M,K] @ B[N,K]^T, bf16 hi/lo 3-MMA, cp.async 3-stage BK=64.
// Block 128x128, 512 thr (16 warps, 32x32 warp tile).
// smem/stage 64KB: Ahi +0, Alo +16K, Bhi +32K, Blo +48K.
// MMA terms issued TERM-MAJOR (all HH, then HL, then LH) so consecutive
// MMAs never share an accumulator (breaks RAW chains).
// ---------------------------------------------------------------------------
template <int EPI>
__global__ __launch_bounds__(512)
void mm2(const uint32_t* __restrict__ Ah, const uint32_t* __restrict__ Al,
         const uint32_t* __restrict__ Bh, const uint32_t* __restrict__ Bl,
         const float* __restrict__ bias, float* __restrict__ Cout,
         uint32_t* __restrict__ qh, uint32_t* __restrict__ ql,
         int N, int K)
{
    extern __shared__ __align__(128) uint32_t sm[];
    const int tid = threadIdx.x, lane = tid & 31, wid = tid >> 5;
    const int m0 = blockIdx.y * 128, n0 = blockIdx.x * 128;
    const int wm = (wid & 3) * 32, wn = (wid >> 2) * 32;
    const uint32_t base = smem_u32(sm);
    const int T  = K >> 6;   // k64 steps
    const int KC = K >> 3;   // 16B chunks per row

    const int arow = lane & 15, aco = lane >> 4;
    const int brow = (lane & 7) | ((lane & 16) >> 1), bco = (lane & 8) >> 3;

    auto issue = [&](int t) {
        int st  = t % 3;
        int kc0 = t << 3;                          // 8 chunks per k64
        #pragma unroll
        for (int it = 0; it < 8; it++) {
            int idx = tid + it * 512;              // 0..4095
            int blk = idx >> 10;                   // 0 Ahi, 1 Alo, 2 Bhi, 3 Blo
            int row = (idx >> 3) & 127;
            int ch  = idx & 7;
            const uint32_t* sp = (blk == 0) ? Ah : (blk == 1) ? Al
                               : (blk == 2) ? Bh : Bl;
            int grow = ((blk >> 1) ? n0 : m0) + row;
            const void* src = sp + ((size_t)grow * KC + kc0 + ch) * 4;
            uint32_t dst = base + st * 65536 + blk * 16384
                         + row * 128 + ((ch ^ (row & 7)) * 16);
            cpa16(dst, src);
        }
    };

    float acc[2][4][4] = {};

    issue(0); CP_COMMIT();
    issue(1); CP_COMMIT();

    for (int t = 0; t < T; t++) {
        if (t + 2 < T) { issue(t + 2); CP_COMMIT(); CP_WAIT(2); }
        else           { CP_WAIT(0); }
        __syncthreads();

        const uint32_t sOff = base + (t % 3) * 65536;
        #pragma unroll
        for (int kk = 0; kk < 4; kk++) {
            uint32_t aH[2][4], aL[2][4], bH[2][4], bL[2][4];
            #pragma unroll
            for (int mt = 0; mt < 2; mt++) {
                int r = wm + mt * 16 + arow;
                int c = (kk * 2 + aco) ^ (r & 7);
                ldsm4(aH[mt], sOff + r * 128 + c * 16);
                ldsm4(aL[mt], sOff + 16384 + r * 128 + c * 16);
            }
            #pragma unroll
            for (int g = 0; g < 2; g++) {
                int r = wn + g * 16 + brow;
                int c = (kk * 2 + bco) ^ (r & 7);
                ldsm4(bH[g], sOff + 32768 + r * 128 + c * 16);
                ldsm4(bL[g], sOff + 49152 + r * 128 + c * 16);
            }
            // Pass 1: HH  (8 independent accumulators)
            #pragma unroll
            for (int mt = 0; mt < 2; mt++)
                #pragma unroll
                for (int nt = 0; nt < 4; nt++)
                    mma_bf(acc[mt][nt], aH[mt], &bH[nt >> 1][(nt & 1) * 2]);
            // Pass 2: HL
            #pragma unroll
            for (int mt = 0; mt < 2; mt++)
                #pragma unroll
                for (int nt = 0; nt < 4; nt++)
                    mma_bf(acc[mt][nt], aH[mt], &bL[nt >> 1][(nt & 1) * 2]);
            // Pass 3: LH
            #pragma unroll
            for (int mt = 0; mt < 2; mt++)
                #pragma unroll
                for (int nt = 0; nt < 4; nt++)
                    mma_bf(acc[mt][nt], aL[mt], &bH[nt >> 1][(nt & 1) * 2]);
        }
        __syncthreads();
    }

    const int r = lane >> 2, j = (lane & 3) * 2;
    if (EPI == 0) {
        const int sidx = n0 >> 10;
        const float qs = (sidx == 0) ? 0.125f : 1.0f;
        uint32_t* H = qh + (size_t)sidx * 2097152;
        uint32_t* L = ql + (size_t)sidx * 2097152;
        #pragma unroll
        for (int mt = 0; mt < 2; mt++) {
            int mA = m0 + wm + mt * 16 + r;
            int b  = mA >> 11, q = mA & 2047;
            #pragma unroll
            for (int nt = 0; nt < 4; nt++) {
                int n = n0 + wn + nt * 8 + j;
                int rin = n & 1023, h = rin >> 6, d = rin & 63;
                size_t o1 = (((size_t)(b * 16 + h)) * 2048 + q) * 32 + (d >> 1);
                uint32_t hh, ll;
                hilo2(acc[mt][nt][0] * qs, acc[mt][nt][1] * qs, hh, ll);
                H[o1] = hh; L[o1] = ll;
                hilo2(acc[mt][nt][2] * qs, acc[mt][nt][3] * qs, hh, ll);
                H[o1 + 8 * 32] = hh; L[o1 + 8 * 32] = ll;
            }
        }
    } else {
        #pragma unroll
        for (int mt = 0; mt < 2; mt++) {
            int mA = m0 + wm + mt * 16 + r;
            #pragma unroll
            for (int nt = 0; nt < 4; nt++) {
                int c = n0 + wn + nt * 8 + j;
                float b0 = bias[c], b1 = bias[c + 1];
                *(float2*)(Cout + (size_t)mA * N + c) =
                    make_float2(acc[mt][nt][0] + b0, acc[mt][nt][1] + b1);
                *(float2*)(Cout + (size_t)(mA + 8) * N + c) =
                    make_float2(acc[mt][nt][2] + b0, acc[mt][nt][3] + b1);
            }
        }
    }
}

// ---------------------------------------------------------------------------
// Flash attention, HMMA hi/lo, cp.async 3-stage 64-key KV ring (1 sync/iter).
// Block = 256 queries of one (b,h), 512 thr / 16 warps (warp owns 16 rows).
// smem (bytes): Qhi 0 (32KB), Qlo 32768; KV stage s at 65536+s*32768:
//   Khi +0, Klo +8192, Vhi +16384, Vlo +24576.  Total 160KB.
// MMA terms issued TERM-MAJOR per kk/kc (pass over all tiles per term).
// ---------------------------------------------------------------------------
__global__ __launch_bounds__(512)
void flash2()
{
    extern __shared__ __align__(128) uint32_t sm[];
    const int tid = threadIdx.x, lane = tid & 31, w = tid >> 5;
    const int bh = blockIdx.y, b = bh >> 4, h = bh & 15;
    const int q0 = blockIdx.x * 256;
    const uint32_t base = smem_u32(sm);

    const int arow = lane & 15, aco = lane >> 4;
    const int brow = (lane & 7) | ((lane & 16) >> 1), bco = (lane & 8) >> 3;

    // Q preload (hi+lo): 4096 16B-chunks
    #pragma unroll
    for (int it = 0; it < 8; it++) {
        int idx = tid + it * 512;
        int lohf = idx >= 2048;
        int row = (idx >> 3) & 255, ch = idx & 7;
        const uint32_t* sp = lohf ? g_qkvl : g_qkvh;
        const void* src = sp + ((size_t)bh * 2048 + q0 + row) * 32 + ch * 4;
        uint32_t dst = base + lohf * 32768 + row * 128 + ((ch ^ (row & 7)) * 16);
        cpa16(dst, src);
    }
    CP_COMMIT();

    auto issueKV = [&](int t) {
        int st = t % 3, s0 = t * 64;
        #pragma unroll
        for (int it = 0; it < 4; it++) {
            int idx = tid + it * 512;              // 0..2047
            int tensor = idx >> 10;                // 0=K, 1=V
            int lohf = (idx >> 9) & 1;
            int row = (idx >> 3) & 63, ch = idx & 7;
            const uint32_t* sp = lohf ? g_qkvl : g_qkvh;
            const void* src = sp + (size_t)(1 + tensor) * 2097152
                            + ((size_t)bh * 2048 + s0 + row) * 32 + ch * 4;
            uint32_t dst = base + 65536 + st * 32768 + tensor * 16384
                         + lohf * 8192 + row * 128 + ((ch ^ (row & 7)) * 16);
            cpa16(dst, src);
        }
    };

    issueKV(0); CP_COMMIT();

    float m_a = -1e30f, m_b = -1e30f, l_a = 0.f, l_b = 0.f;
    float o[8][4] = {};

    const int NT = SEQ / 64;   // 32
    for (int t = 0; t < NT; t++) {
        if (t + 1 < NT) { issueKV(t + 1); CP_COMMIT(); CP_WAIT(1); }
        else            { CP_WAIT(0); }
        __syncthreads();

        const uint32_t kBase = base + 65536 + (t % 3) * 32768;
        const uint32_t vBase = kBase + 16384;

        // S = Q K^T (Q pre-scaled by 0.125). 64 keys = 8 n8 tiles.
        float s[8][4] = {};
        #pragma unroll
        for (int kk = 0; kk < 4; kk++) {
            uint32_t aH[4], aL[4];
            {
                int r = w * 16 + arow;
                int c = (kk * 2 + aco) ^ (r & 7);
                ldsm4(aH, base + r * 128 + c * 16);
                ldsm4(aL, base + 32768 + r * 128 + c * 16);
            }
            // Pass 1: HH over all 4 g-groups (8 independent s-tiles)
            #pragma unroll
            for (int g = 0; g < 4; g++) {
                int rb = g * 16 + brow;
                int cb = (kk * 2 + bco) ^ (rb & 7);
                uint32_t bHf[4];
                ldsm4(bHf, kBase + rb * 128 + cb * 16);
                mma_bf(s[2 * g],     aH, &bHf[0]);
                mma_bf(s[2 * g + 1], aH, &bHf[2]);
            }
            // Pass 2: HL
            #pragma unroll
            for (int g = 0; g < 4; g++) {
                int rb = g * 16 + brow;
                int cb = (kk * 2 + bco) ^ (rb & 7);
                uint32_t bLf[4];
                ldsm4(bLf, kBase + 8192 + rb * 128 + cb * 16);
                mma_bf(s[2 * g],     aH, &bLf[0]);
                mma_bf(s[2 * g + 1], aH, &bLf[2]);
            }
            // Pass 3: LH (re-load K hi fragments)
            #pragma unroll
            for (int g = 0; g < 4; g++) {
                int rb = g * 16 + brow;
                int cb = (kk * 2 + bco) ^ (rb & 7);
                uint32_t bHf[4];
                ldsm4(bHf, kBase + rb * 128 + cb * 16);
                mma_bf(s[2 * g],     aL, &bHf[0]);
                mma_bf(s[2 * g + 1], aL, &bHf[2]);
            }
        }

        // Online softmax (rows lane>>2 and +8; 4-lane group reduce)
        float mxa = -1e30f, mxb = -1e30f;
        #pragma unroll
        for (int nt = 0; nt < 8; nt++) {
            mxa = fmaxf(mxa, fmaxf(s[nt][0], s[nt][1]));
            mxb = fmaxf(mxb, fmaxf(s[nt][2], s[nt][3]));
        }
        mxa = fmaxf(mxa, __shfl_xor_sync(0xffffffffu, mxa, 1));
        mxa = fmaxf(mxa, __shfl_xor_sync(0xffffffffu, mxa, 2));
        mxb = fmaxf(mxb, __shfl_xor_sync(0xffffffffu, mxb, 1));
        mxb = fmaxf(mxb, __shfl_xor_sync(0xffffffffu, mxb, 2));
        float mna = fmaxf(m_a, mxa), mnb = fmaxf(m_b, mxb);
        float alA = __expf(m_a - mna), alB = __expf(m_b - mnb);
        m_a = mna; m_b = mnb;
        float suma = 0.f, sumb = 0.f;
        #pragma unroll
        for (int nt = 0; nt < 8; nt++) {
            s[nt][0] = __expf(s[nt][0] - mna); suma += s[nt][0];
            s[nt][1] = __expf(s[nt][1] - mna); suma += s[nt][1];
            s[nt][2] = __expf(s[nt][2] - mnb); sumb += s[nt][2];
            s[nt][3] = __expf(s[nt][3] - mnb); sumb += s[nt][3];
        }
        suma += __shfl_xor_sync(0xffffffffu, suma, 1);
        suma += __shfl_xor_sync(0xffffffffu, suma, 2);
        sumb += __shfl_xor_sync(0xffffffffu, sumb, 1);
        sumb += __shfl_xor_sync(0xffffffffu, sumb, 2);
        l_a = l_a * alA + suma;
        l_b = l_b * alB + sumb;
        #pragma unroll
        for (int dt = 0; dt < 8; dt++) {
            o[dt][0] *= alA; o[dt][1] *= alA;
            o[dt][2] *= alB; o[dt][3] *= alB;
        }

        // O += P V  (kc = 4 key-chunks of 16; dt = 8 d-tiles), term-major.
        #pragma unroll
        for (int kc = 0; kc < 4; kc++) {
            uint32_t pH[4], pL[4];
            hilo2(s[2 * kc][0],     s[2 * kc][1],     pH[0], pL[0]);
            hilo2(s[2 * kc][2],     s[2 * kc][3],     pH[1], pL[1]);
            hilo2(s[2 * kc + 1][0], s[2 * kc + 1][1], pH[2], pL[2]);
            hilo2(s[2 * kc + 1][2], s[2 * kc + 1][3], pH[3], pL[3]);
            int rv = kc * 16 + arow;
            // Pass 1: pH x vH over all g (8 independent o-tiles)
            #pragma unroll
            for (int g = 0; g < 4; g++) {
                int cv = (g * 2 + aco) ^ (rv & 7);
                uint32_t vHf[4];
                ldsm4t(vHf, vBase + rv * 128 + cv * 16);
                mma_bf(o[2 * g],     pH, &vHf[0]);
                mma_bf(o[2 * g + 1], pH, &vHf[2]);
            }
            // Pass 2: pH x vL
            #pragma unroll
            for (int g = 0; g < 4; g++) {
                int cv = (g * 2 + aco) ^ (rv & 7);
                uint32_t vLf[4];
                ldsm4t(vLf, vBase + 8192 + rv * 128 + cv * 16);
                mma_bf(o[2 * g],     pH, &vLf[0]);
                mma_bf(o[2 * g + 1], pH, &vLf[2]);
            }
            // Pass 3: pL x vH (re-load V hi fragments)
            #pragma unroll
            for (int g = 0; g < 4; g++) {
                int cv = (g * 2 + aco) ^ (rv & 7);
                uint32_t vHf[4];
                ldsm4t(vHf, vBase + rv * 128 + cv * 16);
                mma_bf(o[2 * g],     pL, &vHf[0]);
                mma_bf(o[2 * g + 1], pL, &vHf[2]);
            }
        }
        // NOTE: no bottom barrier — 3-stage KV ring makes it safe.
    }

    // Epilogue: normalize, pack hi/lo to g_aoh/g_aol [m][512]
    float ia = 1.f / l_a, ib = 1.f / l_b;
    size_t mA = (size_t)b * SEQ + q0 + w * 16 + (lane >> 2);
    #pragma unroll
    for (int dt = 0; dt < 8; dt++) {
        int c  = dt * 8 + (lane & 3) * 2;
        int ci = h * 32 + (c >> 1);
        uint32_t hh, ll;
        hilo2(o[dt][0] * ia, o[dt][1] * ia, hh, ll);
        g_aoh[mA * 512 + ci] = hh; g_aol[mA * 512 + ci] = ll;
        hilo2(o[dt][2] * ib, o[dt][3] * ib, hh, ll);
        g_aoh[(mA + 8) * 512 + ci] = hh; g_aol[(mA + 8) * 512 + ci] = ll;
    }
}

// ---------------------------------------------------------------------------
extern "C" void kernel_launch(void* const* d_in, const int* in_sizes, int n_in,
                              void* d_out, int out_size)
{
    const float* x      = (const float*)d_in[0];
    const float* w_qkv  = (const float*)d_in[1];
    const float* w_proj = (const float*)d_in[2];
    const float* b_proj = (const float*)d_in[3];
    float* out = (float*)d_out;

    void *pxh, *pxl, *pwqh, *pwql, *pwph, *pwpl, *pqh, *pql, *paoh, *paol;
    cudaGetSymbolAddress(&pxh, g_xh);   cudaGetSymbolAddress(&pxl, g_xl);
    cudaGetSymbolAddress(&pwqh, g_wqh); cudaGetSymbolAddress(&pwql, g_wql);
    cudaGetSymbolAddress(&pwph, g_wph); cudaGetSymbolAddress(&pwpl, g_wpl);
    cudaGetSymbolAddress(&pqh, g_qkvh); cudaGetSymbolAddress(&pql, g_qkvl);
    cudaGetSymbolAddress(&paoh, g_aoh); cudaGetSymbolAddress(&paol, g_aol);

    cudaFuncSetAttribute(mm2<0>, cudaFuncAttributeMaxDynamicSharedMemorySize, 196608);
    cudaFuncSetAttribute(mm2<1>, cudaFuncAttributeMaxDynamicSharedMemorySize, 196608);
    cudaFuncSetAttribute(flash2, cudaFuncAttributeMaxDynamicSharedMemorySize, 163840);

    // 1) Splits
    split_k<<<4096, 256>>>(x,      (uint32_t*)pxh,  (uint32_t*)pxl,  1048576);
    split_k<<<3072, 256>>>(w_qkv,  (uint32_t*)pwqh, (uint32_t*)pwql, 786432);
    split_k<<<1024, 256>>>(w_proj, (uint32_t*)pwph, (uint32_t*)pwpl, 262144);

    // 2) QKV projection -> split Q/K/V (Q scaled)
    mm2<0><<<dim3(24, 32), 512, 196608>>>(
        (uint32_t*)pxh, (uint32_t*)pxl, (uint32_t*)pwqh, (uint32_t*)pwql,
        nullptr, nullptr, (uint32_t*)pqh, (uint32_t*)pql, 3072, 1024);

    // 3) Attention: 256 queries/block per (b,h)
    flash2<<<dim3(8, 32), 512, 163840>>>();

    // 4) Output projection + bias
    mm2<1><<<dim3(8, 32), 512, 196608>>>(
        (uint32_t*)paoh, (uint32_t*)paol, (uint32_t*)pwph, (uint32_t*)pwpl,
        b_proj, out, nullptr, nullptr, 1024, 1024);
}